// round 12
// baseline (speedup 1.0000x reference)
#include <cuda_runtime.h>
#include <cuda_bf16.h>

#define NODES_MAX 50048
#define EMAX      2000000
#define D 128
#define SCAN_T 1024

// Scratch (alloc-free rule -> __device__ globals)
__device__ int g_idx_is_i64;
__device__ int g_deg[NODES_MAX];
__device__ int g_csr_off[NODES_MAX + 1];
__device__ int g_cursor[NODES_MAX];
__device__ int g_csr_src[EMAX];

__device__ __forceinline__ int load_idx(const void* p, int e) {
    return g_idx_is_i64 ? (int)((const long long*)p)[e] : ((const int*)p)[e];
}

// ---------------------------------------------------------------------------
// Kernel 1: zero degree counters; block 0 also detects index dtype
// (int64 indices < 50000 have all-zero high words; int32 data does not).
// ---------------------------------------------------------------------------
__global__ void zero_detect_kernel(const void* __restrict__ src,
                                   int n, int n_edges) {
    int i = blockIdx.x * blockDim.x + threadIdx.x;
    if (i < n) g_deg[i] = 0;
    if (blockIdx.x == 0) {
        __shared__ int any_hi;
        if (threadIdx.x == 0) any_hi = 0;
        __syncthreads();
        int nsample = n_edges < 128 ? n_edges : 128;
        if (threadIdx.x < nsample) {
            int hi = ((const int*)src)[2 * threadIdx.x + 1];
            if (hi != 0) atomicOr(&any_hi, 1);
        }
        __syncthreads();
        if (threadIdx.x == 0) g_idx_is_i64 = any_hi ? 0 : 1;
    }
}

// ---------------------------------------------------------------------------
// Kernel 2: histogram of dst.
// ---------------------------------------------------------------------------
__global__ void hist_kernel(const void* __restrict__ dst, int n_edges) {
    int e = blockIdx.x * blockDim.x + threadIdx.x;
    if (e >= n_edges) return;
    atomicAdd(&g_deg[load_idx(dst, e)], 1);
}

// ---------------------------------------------------------------------------
// Kernel 3: SINGLE-BLOCK exclusive scan of g_deg -> csr_off, cursor, sentinel.
// Each thread serially scans a contiguous chunk; block-scan of 1024 partials.
// ---------------------------------------------------------------------------
__global__ void scan_all_kernel(int n) {
    __shared__ int s[SCAN_T];
    int t = threadIdx.x;
    int chunk = (n + SCAN_T - 1) / SCAN_T;
    int beg = t * chunk;
    int end = beg + chunk < n ? beg + chunk : n;

    int sum = 0;
    for (int i = beg; i < end; i++) sum += g_deg[i];
    s[t] = sum;
    __syncthreads();
    for (int o = 1; o < SCAN_T; o <<= 1) {
        int x = (t >= o) ? s[t - o] : 0;
        __syncthreads();
        s[t] += x;
        __syncthreads();
    }
    int run = s[t] - sum;          // exclusive prefix at chunk start
    for (int i = beg; i < end; i++) {
        g_csr_off[i] = run;
        g_cursor[i]  = run;
        run += g_deg[i];
    }
    if (t == SCAN_T - 1) g_csr_off[n] = s[SCAN_T - 1];
}

// ---------------------------------------------------------------------------
// Kernel 4: reorder edges into CSR by dst.
// ---------------------------------------------------------------------------
__global__ void reorder_kernel(const void* __restrict__ src,
                               const void* __restrict__ dst, int n_edges) {
    int e = blockIdx.x * blockDim.x + threadIdx.x;
    if (e >= n_edges) return;
    int d = load_idx(dst, e);
    int s = load_idx(src, e);
    int pos = atomicAdd(&g_cursor[d], 1);
    g_csr_src[pos] = s;
}

// ---------------------------------------------------------------------------
// FUSED kernel: out = relu( ((1+eps)*feat + segsum(feat,csr)) @ W^T + b )
// Phase A: 16 warps gather-accumulate h rows into smem (4-way MLP).
// Phase B: scalar 4x4 FFMA register tile (REVERTED from f32x2 — that path
//          regressed 110.8 -> 184.4 us; emulation/reg-spill suspected).
// ---------------------------------------------------------------------------
#define TILE_M 64
#define WPAD 132
#define GEMM_BLOCKS 296

__global__ __launch_bounds__(512, 2) void gin_fused_kernel(
    const float* __restrict__ feat, const float* __restrict__ W,
    const float* __restrict__ bias, const float* __restrict__ eps,
    float* __restrict__ out, int n_nodes) {
    extern __shared__ float sm[];
    float* Wt = sm;               // [128][WPAD]  Wt[k][c] = W[c][k]
    float* hs = sm + D * WPAD;    // [TILE_M][128]

    int tid  = threadIdx.x;
    int lane = tid & 31;
    int wid  = tid >> 5;          // 0..15
    int tx = lane;                // GEMM: output cols 4*tx..4*tx+3
    int ty = wid;                 // GEMM: rows 4*ty..4*ty+3
    float s = 1.0f + eps[0];
    const float4* f4 = (const float4*)feat;

    // Stage W transposed once per block.
    for (int idx = tid; idx < D * D; idx += 512) {
        int c = idx >> 7;
        int k = idx & 127;
        Wt[k * WPAD + c] = W[idx];
    }

    float4 bv = *(const float4*)&bias[tx * 4];
    int n_tiles = (n_nodes + TILE_M - 1) / TILE_M;

    for (int t = blockIdx.x; t < n_tiles; t += gridDim.x) {
        int m0 = t * TILE_M;

        __syncthreads();   // prev iteration's readers done with hs

        // ---- Phase A: gather-accumulate h rows into smem -------------
        for (int r = wid; r < TILE_M; r += 16) {
            int row = m0 + r;
            float4 acc = make_float4(0.f, 0.f, 0.f, 0.f);
            if (row < n_nodes) {
                acc = f4[(size_t)row * 32 + lane];
                acc.x *= s; acc.y *= s; acc.z *= s; acc.w *= s;
                int j = g_csr_off[row], end = g_csr_off[row + 1];
                for (; j + 3 < end; j += 4) {      // 4-way MLP
                    int s0 = g_csr_src[j];
                    int s1 = g_csr_src[j + 1];
                    int s2 = g_csr_src[j + 2];
                    int s3 = g_csr_src[j + 3];
                    float4 v0 = f4[(size_t)s0 * 32 + lane];
                    float4 v1 = f4[(size_t)s1 * 32 + lane];
                    float4 v2 = f4[(size_t)s2 * 32 + lane];
                    float4 v3 = f4[(size_t)s3 * 32 + lane];
                    acc.x += (v0.x + v1.x) + (v2.x + v3.x);
                    acc.y += (v0.y + v1.y) + (v2.y + v3.y);
                    acc.z += (v0.z + v1.z) + (v2.z + v3.z);
                    acc.w += (v0.w + v1.w) + (v2.w + v3.w);
                }
                for (; j < end; j++) {
                    float4 v0 = f4[(size_t)g_csr_src[j] * 32 + lane];
                    acc.x += v0.x; acc.y += v0.y;
                    acc.z += v0.z; acc.w += v0.w;
                }
            }
            ((float4*)(hs + r * D))[lane] = acc;
        }
        __syncthreads();

        // ---- Phase B: scalar 4x4 FFMA register tile ------------------
        float acc[4][4];
#pragma unroll
        for (int i = 0; i < 4; i++)
#pragma unroll
            for (int j = 0; j < 4; j++) acc[i][j] = 0.f;

#pragma unroll 4
        for (int k = 0; k < D; k += 4) {
            float4 w0 = *(const float4*)&Wt[(k + 0) * WPAD + tx * 4];
            float4 w1 = *(const float4*)&Wt[(k + 1) * WPAD + tx * 4];
            float4 w2 = *(const float4*)&Wt[(k + 2) * WPAD + tx * 4];
            float4 w3 = *(const float4*)&Wt[(k + 3) * WPAD + tx * 4];
#pragma unroll
            for (int i = 0; i < 4; i++) {
                float4 hv = *(const float4*)&hs[(ty * 4 + i) * D + k];
                acc[i][0] += hv.x * w0.x + hv.y * w1.x + hv.z * w2.x + hv.w * w3.x;
                acc[i][1] += hv.x * w0.y + hv.y * w1.y + hv.z * w2.y + hv.w * w3.y;
                acc[i][2] += hv.x * w0.z + hv.y * w1.z + hv.z * w2.z + hv.w * w3.z;
                acc[i][3] += hv.x * w0.w + hv.y * w1.w + hv.z * w2.w + hv.w * w3.w;
            }
        }

#pragma unroll
        for (int i = 0; i < 4; i++) {
            int row = m0 + ty * 4 + i;
            if (row < n_nodes) {
                float4 o;
                o.x = fmaxf(acc[i][0] + bv.x, 0.f);
                o.y = fmaxf(acc[i][1] + bv.y, 0.f);
                o.z = fmaxf(acc[i][2] + bv.z, 0.f);
                o.w = fmaxf(acc[i][3] + bv.w, 0.f);
                ((float4*)(out + (size_t)row * D))[tx] = o;
            }
        }
    }
}

// ---------------------------------------------------------------------------
// Launch: zero+detect -> hist -> scan -> reorder -> fused. 5 launches.
// Graph-capturable, alloc-free.
// ---------------------------------------------------------------------------
extern "C" void kernel_launch(void* const* d_in, const int* in_sizes, int n_in,
                              void* d_out, int out_size) {
    const float* feature = (const float*)d_in[0];
    const void*  src     = d_in[1];
    const void*  dst     = d_in[2];
    const float* W       = (const float*)d_in[3];
    const float* bias    = (const float*)d_in[4];
    const float* eps     = (const float*)d_in[5];
    float*       out     = (float*)d_out;

    int n_nodes = in_sizes[0] / D;
    int n_edges = in_sizes[1];

    static bool smem_ok = false;
    size_t smem = (size_t)(D * WPAD + TILE_M * D) * sizeof(float);  // ~100KB
    if (!smem_ok) {
        cudaFuncSetAttribute(gin_fused_kernel,
                             cudaFuncAttributeMaxDynamicSharedMemorySize,
                             (int)smem);
        smem_ok = true;
    }

    zero_detect_kernel<<<(n_nodes + 255) / 256, 256>>>(src, n_nodes, n_edges);
    hist_kernel<<<(n_edges + 255) / 256, 256>>>(dst, n_edges);
    scan_all_kernel<<<1, SCAN_T>>>(n_nodes);
    reorder_kernel<<<(n_edges + 255) / 256, 256>>>(src, dst, n_edges);
    gin_fused_kernel<<<GEMM_BLOCKS, 512, smem>>>(
        feature, W, bias, eps, out, n_nodes);
}

// round 13
// speedup vs baseline: 1.7080x; 1.7080x over previous
#include <cuda_runtime.h>
#include <cuda_bf16.h>

#define NODES_MAX 50048
#define EMAX      2000000
#define D 128
#define SCAN_B 1024

// Scratch (alloc-free rule -> __device__ globals)
__device__ int g_idx_is_i64;
__device__ int g_deg[NODES_MAX];
__device__ int g_scan[NODES_MAX];        // per-block inclusive scans
__device__ int g_blk[64];                // block sums
__device__ int g_blk_exc[64];            // exclusive block offsets
__device__ int g_csr_off[NODES_MAX + 1];
__device__ int g_cursor[NODES_MAX];
__device__ int g_csr_src[EMAX];

__device__ __forceinline__ int load_idx(const void* p, int e) {
    return g_idx_is_i64 ? (int)((const long long*)p)[e] : ((const int*)p)[e];
}

// ---------------------------------------------------------------------------
// Kernel 1: zero degree counters; block 0 also detects index dtype
// (int64 indices < 50000 have all-zero high words; int32 data does not).
// ---------------------------------------------------------------------------
__global__ void zero_detect_kernel(const void* __restrict__ src,
                                   int n, int n_edges) {
    int i = blockIdx.x * blockDim.x + threadIdx.x;
    if (i < n) g_deg[i] = 0;
    if (blockIdx.x == 0) {
        __shared__ int any_hi;
        if (threadIdx.x == 0) any_hi = 0;
        __syncthreads();
        int nsample = n_edges < 128 ? n_edges : 128;
        if (threadIdx.x < nsample) {
            int hi = ((const int*)src)[2 * threadIdx.x + 1];
            if (hi != 0) atomicOr(&any_hi, 1);
        }
        __syncthreads();
        if (threadIdx.x == 0) g_idx_is_i64 = any_hi ? 0 : 1;
    }
}

// ---------------------------------------------------------------------------
// CSR construction: histogram -> scan(x3) -> reorder
// ---------------------------------------------------------------------------
__global__ void hist_kernel(const void* __restrict__ dst, int n_edges) {
    int e = blockIdx.x * blockDim.x + threadIdx.x;
    if (e >= n_edges) return;
    atomicAdd(&g_deg[load_idx(dst, e)], 1);
}

// Per-block inclusive Hillis-Steele scan of g_deg.
__global__ void scan1_kernel(int n) {
    __shared__ int s[SCAN_B];
    int t = threadIdx.x;
    int i = blockIdx.x * SCAN_B + t;
    int v = (i < n) ? g_deg[i] : 0;
    s[t] = v;
    __syncthreads();
    for (int o = 1; o < SCAN_B; o <<= 1) {
        int x = (t >= o) ? s[t - o] : 0;
        __syncthreads();
        s[t] += x;
        __syncthreads();
    }
    if (i < n) g_scan[i] = s[t];
    if (t == SCAN_B - 1) g_blk[blockIdx.x] = s[t];
}

// Single-block scan of block sums -> exclusive block offsets.
__global__ void scan2_kernel(int nblk) {
    __shared__ int s[64];
    int t = threadIdx.x;
    int v = (t < nblk) ? g_blk[t] : 0;
    s[t] = v;
    __syncthreads();
    for (int o = 1; o < 64; o <<= 1) {
        int x = (t >= o) ? s[t - o] : 0;
        __syncthreads();
        s[t] += x;
        __syncthreads();
    }
    if (t < nblk) g_blk_exc[t] = s[t] - v;
}

// Combine: exclusive global offsets; init cursors; write sentinel.
__global__ void scan3_kernel(int n) {
    int i = blockIdx.x * blockDim.x + threadIdx.x;
    if (i >= n) return;
    int off = g_blk_exc[i / SCAN_B] + g_scan[i] - g_deg[i];
    g_csr_off[i] = off;
    g_cursor[i]  = off;
    if (i == n - 1) g_csr_off[n] = off + g_deg[i];
}

__global__ void reorder_kernel(const void* __restrict__ src,
                               const void* __restrict__ dst, int n_edges) {
    int e = blockIdx.x * blockDim.x + threadIdx.x;
    if (e >= n_edges) return;
    int d = load_idx(dst, e);
    int s = load_idx(src, e);
    int pos = atomicAdd(&g_cursor[d], 1);
    g_csr_src[pos] = s;
}

// ---------------------------------------------------------------------------
// FUSED kernel: out = relu( ((1+eps)*feat + segsum(feat,csr)) @ W^T + b )
// Phase A: 16 warps gather-accumulate h rows into smem (2-way MLP).
// Phase B: scalar 4x4 FFMA register tile.
// EXACT Round-6 build (measured 110.8us) — bisect anchor.
// ---------------------------------------------------------------------------
#define TILE_M 64
#define WPAD 132
#define GEMM_BLOCKS 296

__global__ __launch_bounds__(512, 2) void gin_fused_kernel(
    const float* __restrict__ feat, const float* __restrict__ W,
    const float* __restrict__ bias, const float* __restrict__ eps,
    float* __restrict__ out, int n_nodes) {
    extern __shared__ float sm[];
    float* Wt = sm;               // [128][WPAD]  Wt[k][c] = W[c][k]
    float* hs = sm + D * WPAD;    // [TILE_M][128]

    int tid  = threadIdx.x;
    int lane = tid & 31;
    int wid  = tid >> 5;          // 0..15
    int tx = lane;                // GEMM: output cols 4*tx..4*tx+3
    int ty = wid;                 // GEMM: rows 4*ty..4*ty+3
    float s = 1.0f + eps[0];
    const float4* f4 = (const float4*)feat;

    // Stage W transposed once per block.
    for (int idx = tid; idx < D * D; idx += 512) {
        int c = idx >> 7;
        int k = idx & 127;
        Wt[k * WPAD + c] = W[idx];
    }

    float4 bv = *(const float4*)&bias[tx * 4];
    int n_tiles = (n_nodes + TILE_M - 1) / TILE_M;

    for (int t = blockIdx.x; t < n_tiles; t += gridDim.x) {
        int m0 = t * TILE_M;

        __syncthreads();   // prev iteration's readers done with hs

        // ---- Phase A: gather-accumulate h rows into smem -------------
        for (int r = wid; r < TILE_M; r += 16) {
            int row = m0 + r;
            float4 acc = make_float4(0.f, 0.f, 0.f, 0.f);
            if (row < n_nodes) {
                acc = f4[(size_t)row * 32 + lane];
                acc.x *= s; acc.y *= s; acc.z *= s; acc.w *= s;
                int j = g_csr_off[row], end = g_csr_off[row + 1];
                for (; j + 1 < end; j += 2) {      // 2-way unroll for MLP
                    int s0 = g_csr_src[j];
                    int s1 = g_csr_src[j + 1];
                    float4 v0 = f4[(size_t)s0 * 32 + lane];
                    float4 v1 = f4[(size_t)s1 * 32 + lane];
                    acc.x += v0.x + v1.x;
                    acc.y += v0.y + v1.y;
                    acc.z += v0.z + v1.z;
                    acc.w += v0.w + v1.w;
                }
                if (j < end) {
                    float4 v0 = f4[(size_t)g_csr_src[j] * 32 + lane];
                    acc.x += v0.x; acc.y += v0.y;
                    acc.z += v0.z; acc.w += v0.w;
                }
            }
            ((float4*)(hs + r * D))[lane] = acc;
        }
        __syncthreads();

        // ---- Phase B: 4x4 register-tile GEMM from smem ---------------
        float acc[4][4];
#pragma unroll
        for (int i = 0; i < 4; i++)
#pragma unroll
            for (int j = 0; j < 4; j++) acc[i][j] = 0.f;

#pragma unroll 4
        for (int k = 0; k < D; k += 4) {
            float4 w0 = *(const float4*)&Wt[(k + 0) * WPAD + tx * 4];
            float4 w1 = *(const float4*)&Wt[(k + 1) * WPAD + tx * 4];
            float4 w2 = *(const float4*)&Wt[(k + 2) * WPAD + tx * 4];
            float4 w3 = *(const float4*)&Wt[(k + 3) * WPAD + tx * 4];
#pragma unroll
            for (int i = 0; i < 4; i++) {
                float4 hv = *(const float4*)&hs[(ty * 4 + i) * D + k];
                acc[i][0] += hv.x * w0.x + hv.y * w1.x + hv.z * w2.x + hv.w * w3.x;
                acc[i][1] += hv.x * w0.y + hv.y * w1.y + hv.z * w2.y + hv.w * w3.y;
                acc[i][2] += hv.x * w0.z + hv.y * w1.z + hv.z * w2.z + hv.w * w3.z;
                acc[i][3] += hv.x * w0.w + hv.y * w1.w + hv.z * w2.w + hv.w * w3.w;
            }
        }

#pragma unroll
        for (int i = 0; i < 4; i++) {
            int row = m0 + ty * 4 + i;
            if (row < n_nodes) {
                float4 o;
                o.x = fmaxf(acc[i][0] + bv.x, 0.f);
                o.y = fmaxf(acc[i][1] + bv.y, 0.f);
                o.z = fmaxf(acc[i][2] + bv.z, 0.f);
                o.w = fmaxf(acc[i][3] + bv.w, 0.f);
                ((float4*)(out + (size_t)row * D))[tx] = o;
            }
        }
    }
}

// ---------------------------------------------------------------------------
// Launch: zero+detect -> hist -> scan x3 -> reorder -> fused gemm.
// Graph-capturable, alloc-free.
// ---------------------------------------------------------------------------
extern "C" void kernel_launch(void* const* d_in, const int* in_sizes, int n_in,
                              void* d_out, int out_size) {
    const float* feature = (const float*)d_in[0];
    const void*  src     = d_in[1];
    const void*  dst     = d_in[2];
    const float* W       = (const float*)d_in[3];
    const float* bias    = (const float*)d_in[4];
    const float* eps     = (const float*)d_in[5];
    float*       out     = (float*)d_out;

    int n_nodes = in_sizes[0] / D;
    int n_edges = in_sizes[1];

    static bool smem_ok = false;
    size_t smem = (size_t)(D * WPAD + TILE_M * D) * sizeof(float);  // ~100KB
    if (!smem_ok) {
        cudaFuncSetAttribute(gin_fused_kernel,
                             cudaFuncAttributeMaxDynamicSharedMemorySize,
                             (int)smem);
        smem_ok = true;
    }

    int nblk_scan = (n_nodes + SCAN_B - 1) / SCAN_B;  // 49 for 50k

    // CSR build
    zero_detect_kernel<<<(n_nodes + 255) / 256, 256>>>(src, n_nodes, n_edges);
    hist_kernel<<<(n_edges + 255) / 256, 256>>>(dst, n_edges);
    scan1_kernel<<<nblk_scan, SCAN_B>>>(n_nodes);
    scan2_kernel<<<1, 64>>>(nblk_scan);
    scan3_kernel<<<(n_nodes + 255) / 256, 256>>>(n_nodes);
    reorder_kernel<<<(n_edges + 255) / 256, 256>>>(src, dst, n_edges);

    // Fused gather-accumulate + GEMM + bias + relu
    gin_fused_kernel<<<GEMM_BLOCKS, 512, smem>>>(
        feature, W, bias, eps, out, n_nodes);
}